// round 1
// baseline (speedup 1.0000x reference)
#include <cuda_runtime.h>
#include <stdint.h>

// ROISelect: per-row top-k(score) + ROI gather.
//   score: [128, 131072] f32
//   roi:   [128, 131072, 4] f32
//   out:   roi_selected [128,256,4] f32  followed by  top_k_score [128,256] f32
//
// One CTA per row. Single coalesced pass collects candidates >= 2.5 (statistical
// threshold with >20-sigma margin for N(0,1) data) into shared memory, then an
// in-smem bitonic sort of packed (sortable_u32 << 32 | ~index) keys yields the
// exact sorted top-256. An exact 12-bit radix-select fallback guarantees
// correctness if the threshold guess ever fails.

#define B_ROWS 128
#define N_COLS 131072
#define K_TOP  256
#define TPB    1024
#define CAP    4096
#define VEC_ITERS (N_COLS / 4 / TPB)   // 32 float4 per thread

__device__ __forceinline__ unsigned int f2u(float f) {
    unsigned int b = __float_as_uint(f);
    return (b & 0x80000000u) ? ~b : (b | 0x80000000u);
}
__device__ __forceinline__ float u2f(unsigned int u) {
    unsigned int b = (u & 0x80000000u) ? (u ^ 0x80000000u) : ~u;
    return __uint_as_float(b);
}

__global__ __launch_bounds__(TPB, 1)
void roiselect_topk_kernel(const float* __restrict__ score,
                           const float* __restrict__ roi,
                           float* __restrict__ out_roi,
                           float* __restrict__ out_score)
{
    __shared__ int s_count;
    __shared__ int s_bin;
    extern __shared__ unsigned long long cand[];   // CAP entries = 32 KB

    const int tid = threadIdx.x;
    const int row = blockIdx.x;
    const float4* sc4 = (const float4*)(score + (size_t)row * N_COLS);

    if (tid == 0) s_count = 0;
    __syncthreads();

    // ---------- Fast path: single scan, collect score >= 2.5 ----------
    const float TGUESS = 2.5f;
    #pragma unroll 4
    for (int i = 0; i < VEC_ITERS; ++i) {
        int v4 = tid + i * TPB;
        float4 f = sc4[v4];
        int base = v4 * 4;
        float vals[4] = {f.x, f.y, f.z, f.w};
        #pragma unroll
        for (int c = 0; c < 4; ++c) {
            if (vals[c] >= TGUESS) {
                unsigned int u = __float_as_uint(vals[c]) | 0x80000000u;
                int pos = atomicAdd(&s_count, 1);
                if (pos < CAP)
                    cand[pos] = ((unsigned long long)u << 32)
                              | (unsigned int)~(unsigned int)(base + c);
            }
        }
    }
    __syncthreads();
    int count = s_count;

    // ---------- Exact fallback: 12-bit radix select (never taken on this data) ----------
    if (count < K_TOP || count > CAP) {
        unsigned int* hist  = (unsigned int*)cand;   // 4096 bins
        unsigned int* sdata = hist + 4096;           // 1024 thread sums
        for (int i = tid; i < 4096; i += TPB) hist[i] = 0;
        if (tid == 0) s_count = 0;
        __syncthreads();

        for (int i = 0; i < VEC_ITERS; ++i) {
            float4 f = sc4[tid + i * TPB];
            float vals[4] = {f.x, f.y, f.z, f.w};
            #pragma unroll
            for (int c = 0; c < 4; ++c)
                atomicAdd(&hist[f2u(vals[c]) >> 20], 1u);
        }
        __syncthreads();

        unsigned int h0 = hist[4*tid+0], h1 = hist[4*tid+1];
        unsigned int h2 = hist[4*tid+2], h3 = hist[4*tid+3];
        sdata[tid] = h0 + h1 + h2 + h3;
        __syncthreads();
        // Hillis-Steele inclusive suffix scan over thread sums
        for (int d = 1; d < TPB; d <<= 1) {
            unsigned int v = (tid + d < TPB) ? sdata[tid + d] : 0u;
            __syncthreads();
            sdata[tid] += v;
            __syncthreads();
        }
        unsigned int Anext = (tid + 1 < TPB) ? sdata[tid + 1] : 0u;
        unsigned int cum3 = Anext + h3;
        unsigned int cum2 = cum3 + h2;
        unsigned int cum1 = cum2 + h1;
        unsigned int cum0 = cum1 + h0;
        if (cum3 >= K_TOP && Anext < K_TOP) s_bin = 4*tid + 3;
        if (cum2 >= K_TOP && cum3  < K_TOP) s_bin = 4*tid + 2;
        if (cum1 >= K_TOP && cum2  < K_TOP) s_bin = 4*tid + 1;
        if (cum0 >= K_TOP && cum1  < K_TOP) s_bin = 4*tid + 0;
        __syncthreads();
        unsigned int uthr = (unsigned int)s_bin << 20;
        __syncthreads();   // everyone has uthr; safe to overwrite hist region

        for (int i = 0; i < VEC_ITERS; ++i) {
            int v4 = tid + i * TPB;
            float4 f = sc4[v4];
            int base = v4 * 4;
            float vals[4] = {f.x, f.y, f.z, f.w};
            #pragma unroll
            for (int c = 0; c < 4; ++c) {
                unsigned int u = f2u(vals[c]);
                if (u >= uthr) {
                    int pos = atomicAdd(&s_count, 1);
                    if (pos < CAP)
                        cand[pos] = ((unsigned long long)u << 32)
                                  | (unsigned int)~(unsigned int)(base + c);
                }
            }
        }
        __syncthreads();
        count = min(s_count, CAP);
    }

    // ---------- Pad to power of two ----------
    int n = K_TOP;
    while (n < count) n <<= 1;
    for (int i = count + tid; i < n; i += TPB) cand[i] = 0ULL;
    __syncthreads();

    // ---------- Bitonic sort, descending ----------
    for (int size = 2; size <= n; size <<= 1) {
        for (int stride = size >> 1; stride > 0; stride >>= 1) {
            for (int i = tid; i < n; i += TPB) {
                int j = i ^ stride;
                if (j > i) {
                    unsigned long long a = cand[i];
                    unsigned long long b = cand[j];
                    bool desc = ((i & size) == 0);
                    if (desc ? (a < b) : (a > b)) { cand[i] = b; cand[j] = a; }
                }
            }
            __syncthreads();
        }
    }

    // ---------- Emit top-256: sorted scores + ROI gather ----------
    if (tid < K_TOP) {
        unsigned long long p = cand[tid];
        unsigned int u   = (unsigned int)(p >> 32);
        unsigned int idx = ~(unsigned int)p;
        out_score[row * K_TOP + tid] = u2f(u);
        const float4* r4 = (const float4*)roi;
        float4 rv = r4[(size_t)row * N_COLS + idx];
        ((float4*)out_roi)[row * K_TOP + tid] = rv;
    }
}

extern "C" void kernel_launch(void* const* d_in, const int* in_sizes, int n_in,
                              void* d_out, int out_size) {
    (void)in_sizes; (void)n_in; (void)out_size;
    const float* score = (const float*)d_in[0];
    const float* roi   = (const float*)d_in[1];
    float* out_roi   = (float*)d_out;                               // [128,256,4]
    float* out_score = (float*)d_out + (size_t)B_ROWS * K_TOP * 4;  // [128,256]
    roiselect_topk_kernel<<<B_ROWS, TPB, CAP * sizeof(unsigned long long)>>>(
        score, roi, out_roi, out_score);
}